// round 7
// baseline (speedup 1.0000x reference)
#include <cuda_runtime.h>
#include <cstdint>

#define THREADS 128
#define SPT 2
#define SPB (THREADS * SPT)   // 256 samples per block

// Packed fp32x2 FMA (sm_103a FFMA2) — only reachable via PTX.
#define FFMA2(D, A, B, C) \
    asm("fma.rn.f32x2 %0, %1, %2, %3;" : "=l"(D) : "l"(A), "l"(B), "l"(C))
#define PACK2(D, LO, HI) \
    asm("mov.b64 %0, {%1, %2};" : "=l"(D) : "f"(LO), "f"(HI))
#define UNPACK2(LO, HI, S) \
    asm("mov.b64 {%0, %1}, %2;" : "=f"(LO), "=f"(HI) : "l"(S))

// Soft-tree node: w*min + (1-w)*max == max - w*|a-b|  (FADD+FMNMX+FFMA)
__device__ __forceinline__ float node(float a, float b, float w) {
    return fmaf(w, -fabsf(a - b), fmaxf(a, b));
}

__global__ void __launch_bounds__(THREADS)
bacon_forest_kernel(const float* __restrict__ c20,
                    const float* __restrict__ w_raw,
                    float* __restrict__ out,
                    int B)
{
    // Layer-0 weights, NEGATED and DUPLICATED: dw0[t][j] = (-w, -w).
    // Row = 10 float2 = 80B (16B-aligned) -> 5x LDS.128 gives packed u64 pairs.
    __shared__ __align__(16) float2 dw0[19 * 10];
    // Upper weights (cols 10..18) padded to 12 floats/row -> 3x LDS.128.
    __shared__ __align__(16) float swu[19 * 12];
    // One buffer, two lives: input stage (SPB*20), then output stage (SPB*19).
    __shared__ __align__(16) float buf[SPB * 20];

    const int tid = threadIdx.x;

    for (int i = tid; i < 19 * 19; i += THREADS) {
        int r = i / 19;
        int c = i - r * 19;
        float raw = __ldg(&w_raw[i]);
        float s = 1.0f / (1.0f + __expf(-raw));
        if (c < 10) dw0[r * 10 + c] = make_float2(-s, -s);
        else        swu[r * 12 + (c - 10)] = s;
    }
    // zero the swu pad lanes (9..11) so LDS.128 reads defined data
    for (int i = tid; i < 19 * 3; i += THREADS) {
        int r = i / 3;
        swu[r * 12 + 9 + (i - r * 3)] = 0.0f;
    }

    const int base = blockIdx.x * SPB;
    const int nS   = min(SPB, B - base);

    // Coalesced input staging (block region contiguous, 16B-aligned).
    {
        const float4* g4 = reinterpret_cast<const float4*>(c20 + (size_t)base * 20);
        float4*       b4 = reinterpret_cast<float4*>(buf);
        const int nV = nS * 5;
        for (int i = tid; i < nV; i += THREADS)
            b4[i] = g4[i];
    }
    __syncthreads();

    // Per-thread samples s0=tid, s1=tid+THREADS. Build packed tree-invariants:
    // m2[j] = (max_s0, max_s1), ad2[j] = (|a-b|_s0, |a-b|_s1).
    uint64_t m2[10], ad2[10];
    {
        float mx[2][10], ad[2][10];
        #pragma unroll
        for (int s = 0; s < 2; ++s) {
            const float4* xp = reinterpret_cast<const float4*>(&buf[(tid + s * THREADS) * 20]);
            float4 q0 = xp[0], q1 = xp[1], q2 = xp[2], q3 = xp[3], q4 = xp[4];
            float x[20] = { q0.x, q0.y, q0.z, q0.w,  q1.x, q1.y, q1.z, q1.w,
                            q2.x, q2.y, q2.z, q2.w,  q3.x, q3.y, q3.z, q3.w,
                            q4.x, q4.y, q4.z, q4.w };
            #pragma unroll
            for (int j = 0; j < 10; ++j) {
                float a = x[2 * j], b = x[2 * j + 1];
                mx[s][j] = fmaxf(a, b);
                ad[s][j] = fabsf(a - b);
            }
        }
        #pragma unroll
        for (int j = 0; j < 10; ++j) {
            PACK2(m2[j],  mx[0][j], mx[1][j]);
            PACK2(ad2[j], ad[0][j], ad[1][j]);
        }
    }
    __syncthreads();    // input reads done before buf is reused for outputs

    #pragma unroll
    for (int t = 0; t < 19; ++t) {
        // Layer-0 weights: 5x LDS.128 -> 10 packed (-w,-w) u64s, no pack instrs.
        const ulonglong2* dwp = reinterpret_cast<const ulonglong2*>(&dw0[t * 10]);
        ulonglong2 P0 = dwp[0], P1 = dwp[1], P2 = dwp[2], P3 = dwp[3], P4 = dwp[4];
        // Upper weights cols 10..18: 3x LDS.128.
        const float4* up = reinterpret_cast<const float4*>(&swu[t * 12]);
        float4 u0 = up[0], u1 = up[1], u2 = up[2];

        // Layer 0 (20 -> 10), both samples per instruction: y2 = fma2(-w, |d|, max)
        uint64_t Y[10];
        FFMA2(Y[0], P0.x, ad2[0], m2[0]);
        FFMA2(Y[1], P0.y, ad2[1], m2[1]);
        FFMA2(Y[2], P1.x, ad2[2], m2[2]);
        FFMA2(Y[3], P1.y, ad2[3], m2[3]);
        FFMA2(Y[4], P2.x, ad2[4], m2[4]);
        FFMA2(Y[5], P2.y, ad2[5], m2[5]);
        FFMA2(Y[6], P3.x, ad2[6], m2[6]);
        FFMA2(Y[7], P3.y, ad2[7], m2[7]);
        FFMA2(Y[8], P4.x, ad2[8], m2[8]);
        FFMA2(Y[9], P4.y, ad2[9], m2[9]);

        #pragma unroll
        for (int s = 0; s < 2; ++s) {
            float y0, y1, y2, y3, y4, y5, y6, y7, y8, y9, dead;
            if (s == 0) {
                UNPACK2(y0, dead, Y[0]); UNPACK2(y1, dead, Y[1]);
                UNPACK2(y2, dead, Y[2]); UNPACK2(y3, dead, Y[3]);
                UNPACK2(y4, dead, Y[4]); UNPACK2(y5, dead, Y[5]);
                UNPACK2(y6, dead, Y[6]); UNPACK2(y7, dead, Y[7]);
                UNPACK2(y8, dead, Y[8]); UNPACK2(y9, dead, Y[9]);
            } else {
                UNPACK2(dead, y0, Y[0]); UNPACK2(dead, y1, Y[1]);
                UNPACK2(dead, y2, Y[2]); UNPACK2(dead, y3, Y[3]);
                UNPACK2(dead, y4, Y[4]); UNPACK2(dead, y5, Y[5]);
                UNPACK2(dead, y6, Y[6]); UNPACK2(dead, y7, Y[7]);
                UNPACK2(dead, y8, Y[8]); UNPACK2(dead, y9, Y[9]);
            }

            // Layer 1 (10 -> 5): cols 10..14
            float z0 = node(y0, y1, u0.x);
            float z1 = node(y2, y3, u0.y);
            float z2 = node(y4, y5, u0.z);
            float z3 = node(y6, y7, u0.w);
            float z4 = node(y8, y9, u1.x);

            // Layer 2 (5 -> 2, carry z4): cols 15,16
            float v0 = node(z0, z1, u1.y);
            float v1 = node(z2, z3, u1.z);

            // Layer 3 (3 -> 1, carry z4): col 17
            float r0 = node(v0, v1, u1.w);

            // Layer 4 (2 -> 1): col 18
            float o = node(r0, z4, u2.x);

            o = fminf(fmaxf(o, 1e-6f), 1.0f - 1e-6f);
            buf[(tid + s * THREADS) * 19 + t] = o;   // stride 19: conflict-free
        }
    }
    __syncthreads();

    // Coalesced writeback of nS*19 floats (base*19 is 16B-aligned).
    const int nFlt = nS * 19;
    const int nVec = nFlt >> 2;
    float*        og = out + (size_t)base * 19;
    float4*       o4 = reinterpret_cast<float4*>(og);
    const float4* s4 = reinterpret_cast<const float4*>(buf);

    for (int i = tid; i < nVec; i += THREADS)
        o4[i] = s4[i];
    for (int i = (nVec << 2) + tid; i < nFlt; i += THREADS)
        og[i] = buf[i];
}

extern "C" void kernel_launch(void* const* d_in, const int* in_sizes, int n_in,
                              void* d_out, int out_size) {
    // metadata order: p1 (int32), p2 (int32), c20 (float32, B*20), w_raw (float32, 361)
    const float* c20   = (const float*)d_in[2];
    const float* w_raw = (const float*)d_in[3];
    float* out = (float*)d_out;
    int B = in_sizes[2] / 20;
    int grid = (B + SPB - 1) / SPB;
    bacon_forest_kernel<<<grid, THREADS>>>(c20, w_raw, out, B);
}

// round 8
// speedup vs baseline: 1.0067x; 1.0067x over previous
#include <cuda_runtime.h>
#include <cstdint>

#define THREADS 128
#define SPT 2
#define SPB (THREADS * SPT)   // 256 samples per block

// Packed fp32x2 FMA (sm_103a FFMA2) — only reachable via PTX.
#define FFMA2(D, A, B, C) \
    asm("fma.rn.f32x2 %0, %1, %2, %3;" : "=l"(D) : "l"(A), "l"(B), "l"(C))
#define PACK2(D, LO, HI) \
    asm("mov.b64 %0, {%1, %2};" : "=l"(D) : "f"(LO), "f"(HI))
#define UNPACK2(LO, HI, S) \
    asm("mov.b64 {%0, %1}, %2;" : "=f"(LO), "=f"(HI) : "l"(S))

// Soft-tree node: w*min + (1-w)*max == max - w*|a-b|  (FADD+FMNMX+FFMA)
__device__ __forceinline__ float node(float a, float b, float w) {
    return fmaf(w, -fabsf(a - b), fmaxf(a, b));
}

__global__ void __launch_bounds__(THREADS)
bacon_forest_kernel(const float* __restrict__ c20,
                    const float* __restrict__ w_raw,
                    float* __restrict__ out,
                    int B)
{
    // Layer-0 weights, NEGATED and DUPLICATED: dw0[t][j] = (-w, -w).
    // Row = 10 float2 = 80B (16B-aligned) -> 5x LDS.128 gives packed u64 pairs.
    __shared__ __align__(16) float2 dw0[19 * 10];
    // Upper weights (cols 10..18) padded to 12 floats/row -> 3x LDS.128.
    __shared__ __align__(16) float swu[19 * 12];
    // One buffer, two lives: input stage (SPB*20), then output stage (SPB*19).
    __shared__ __align__(16) float buf[SPB * 20];

    const int tid = threadIdx.x;

    for (int i = tid; i < 19 * 19; i += THREADS) {
        int r = i / 19;
        int c = i - r * 19;
        float raw = __ldg(&w_raw[i]);
        float s = 1.0f / (1.0f + __expf(-raw));
        if (c < 10) dw0[r * 10 + c] = make_float2(-s, -s);
        else        swu[r * 12 + (c - 10)] = s;
    }
    // zero the swu pad lanes (9..11) so LDS.128 reads defined data
    for (int i = tid; i < 19 * 3; i += THREADS) {
        int r = i / 3;
        swu[r * 12 + 9 + (i - r * 3)] = 0.0f;
    }

    const int base = blockIdx.x * SPB;
    const int nS   = min(SPB, B - base);

    // Coalesced input staging (block region contiguous, 16B-aligned).
    {
        const float4* g4 = reinterpret_cast<const float4*>(c20 + (size_t)base * 20);
        float4*       b4 = reinterpret_cast<float4*>(buf);
        const int nV = nS * 5;
        for (int i = tid; i < nV; i += THREADS)
            b4[i] = g4[i];
    }
    __syncthreads();

    // Per-thread samples s0=tid, s1=tid+THREADS. Build packed tree-invariants:
    // m2[j] = (max_s0, max_s1), ad2[j] = (|a-b|_s0, |a-b|_s1).
    uint64_t m2[10], ad2[10];
    {
        float mx[2][10], ad[2][10];
        #pragma unroll
        for (int s = 0; s < 2; ++s) {
            const float4* xp = reinterpret_cast<const float4*>(&buf[(tid + s * THREADS) * 20]);
            float4 q0 = xp[0], q1 = xp[1], q2 = xp[2], q3 = xp[3], q4 = xp[4];
            float x[20] = { q0.x, q0.y, q0.z, q0.w,  q1.x, q1.y, q1.z, q1.w,
                            q2.x, q2.y, q2.z, q2.w,  q3.x, q3.y, q3.z, q3.w,
                            q4.x, q4.y, q4.z, q4.w };
            #pragma unroll
            for (int j = 0; j < 10; ++j) {
                float a = x[2 * j], b = x[2 * j + 1];
                mx[s][j] = fmaxf(a, b);
                ad[s][j] = fabsf(a - b);
            }
        }
        #pragma unroll
        for (int j = 0; j < 10; ++j) {
            PACK2(m2[j],  mx[0][j], mx[1][j]);
            PACK2(ad2[j], ad[0][j], ad[1][j]);
        }
    }
    __syncthreads();    // input reads done before buf is reused for outputs

    #pragma unroll
    for (int t = 0; t < 19; ++t) {
        // Layer-0 weights: 5x LDS.128 -> 10 packed (-w,-w) u64s, no pack instrs.
        const ulonglong2* dwp = reinterpret_cast<const ulonglong2*>(&dw0[t * 10]);
        ulonglong2 P0 = dwp[0], P1 = dwp[1], P2 = dwp[2], P3 = dwp[3], P4 = dwp[4];
        // Upper weights cols 10..18: 3x LDS.128.
        const float4* up = reinterpret_cast<const float4*>(&swu[t * 12]);
        float4 u0 = up[0], u1 = up[1], u2 = up[2];

        // Layer 0 (20 -> 10), both samples per instruction: y2 = fma2(-w, |d|, max)
        uint64_t Y[10];
        FFMA2(Y[0], P0.x, ad2[0], m2[0]);
        FFMA2(Y[1], P0.y, ad2[1], m2[1]);
        FFMA2(Y[2], P1.x, ad2[2], m2[2]);
        FFMA2(Y[3], P1.y, ad2[3], m2[3]);
        FFMA2(Y[4], P2.x, ad2[4], m2[4]);
        FFMA2(Y[5], P2.y, ad2[5], m2[5]);
        FFMA2(Y[6], P3.x, ad2[6], m2[6]);
        FFMA2(Y[7], P3.y, ad2[7], m2[7]);
        FFMA2(Y[8], P4.x, ad2[8], m2[8]);
        FFMA2(Y[9], P4.y, ad2[9], m2[9]);

        #pragma unroll
        for (int s = 0; s < 2; ++s) {
            float y0, y1, y2, y3, y4, y5, y6, y7, y8, y9, dead;
            if (s == 0) {
                UNPACK2(y0, dead, Y[0]); UNPACK2(y1, dead, Y[1]);
                UNPACK2(y2, dead, Y[2]); UNPACK2(y3, dead, Y[3]);
                UNPACK2(y4, dead, Y[4]); UNPACK2(y5, dead, Y[5]);
                UNPACK2(y6, dead, Y[6]); UNPACK2(y7, dead, Y[7]);
                UNPACK2(y8, dead, Y[8]); UNPACK2(y9, dead, Y[9]);
            } else {
                UNPACK2(dead, y0, Y[0]); UNPACK2(dead, y1, Y[1]);
                UNPACK2(dead, y2, Y[2]); UNPACK2(dead, y3, Y[3]);
                UNPACK2(dead, y4, Y[4]); UNPACK2(dead, y5, Y[5]);
                UNPACK2(dead, y6, Y[6]); UNPACK2(dead, y7, Y[7]);
                UNPACK2(dead, y8, Y[8]); UNPACK2(dead, y9, Y[9]);
            }

            // Layer 1 (10 -> 5): cols 10..14
            float z0 = node(y0, y1, u0.x);
            float z1 = node(y2, y3, u0.y);
            float z2 = node(y4, y5, u0.z);
            float z3 = node(y6, y7, u0.w);
            float z4 = node(y8, y9, u1.x);

            // Layer 2 (5 -> 2, carry z4): cols 15,16
            float v0 = node(z0, z1, u1.y);
            float v1 = node(z2, z3, u1.z);

            // Layer 3 (3 -> 1, carry z4): col 17
            float r0 = node(v0, v1, u1.w);

            // Layer 4 (2 -> 1): col 18
            float o = node(r0, z4, u2.x);

            o = fminf(fmaxf(o, 1e-6f), 1.0f - 1e-6f);
            buf[(tid + s * THREADS) * 19 + t] = o;   // stride 19: conflict-free
        }
    }
    __syncthreads();

    // Coalesced writeback of nS*19 floats (base*19 is 16B-aligned).
    const int nFlt = nS * 19;
    const int nVec = nFlt >> 2;
    float*        og = out + (size_t)base * 19;
    float4*       o4 = reinterpret_cast<float4*>(og);
    const float4* s4 = reinterpret_cast<const float4*>(buf);

    for (int i = tid; i < nVec; i += THREADS)
        o4[i] = s4[i];
    for (int i = (nVec << 2) + tid; i < nFlt; i += THREADS)
        og[i] = buf[i];
}

extern "C" void kernel_launch(void* const* d_in, const int* in_sizes, int n_in,
                              void* d_out, int out_size) {
    // metadata order: p1 (int32), p2 (int32), c20 (float32, B*20), w_raw (float32, 361)
    const float* c20   = (const float*)d_in[2];
    const float* w_raw = (const float*)d_in[3];
    float* out = (float*)d_out;
    int B = in_sizes[2] / 20;
    int grid = (B + SPB - 1) / SPB;
    bacon_forest_kernel<<<grid, THREADS>>>(c20, w_raw, out, B);
}